// round 12
// baseline (speedup 1.0000x reference)
#include <cuda_runtime.h>
#include <cstdint>

#define Nn   64
#define Cc   256
#define HWs  3136
#define Gg   16
#define Mf   200704.0f
#define EPSf 1e-3f

#define SLICES 148
#define APPLY_BLOCKS 296
#define NWARPS (APPLY_BLOCKS * 8)        // 2368 warps
#define SLABS_PER_COL 196                // 3136 / 16
#define TOT_SLABS (1024 * SLABS_PER_COL) // 200704
#define BASE_CNT 84                      // 84*2368 = 198912; remainder 1792

// Scratch (static device globals — no allocation)
__device__ float g_sig[Gg][SLICES][16][16];
__device__ float g_sum[Gg][SLICES][16];
__device__ float g_A[Gg][16][16];
__device__ float g_beta[Gg][16];

// ---------------- helpers ----------------
__device__ __forceinline__ uint32_t to_tf32(float f) {
    uint32_t u;
    asm("cvt.rna.tf32.f32 %0, %1;" : "=r"(u) : "f"(f));
    return u;
}

__device__ __forceinline__ void mma_tf32(float* c, uint32_t a0, uint32_t a1,
                                         uint32_t a2, uint32_t a3,
                                         uint32_t b0, uint32_t b1) {
    asm("mma.sync.aligned.m16n8k8.row.col.f32.tf32.tf32.f32 "
        "{%0,%1,%2,%3}, {%4,%5,%6,%7}, {%8,%9}, {%0,%1,%2,%3};"
        : "+f"(c[0]), "+f"(c[1]), "+f"(c[2]), "+f"(c[3])
        : "r"(a0), "r"(a1), "r"(a2), "r"(a3), "r"(b0), "r"(b1));
}

// split f32 -> (tf32 hi, tf32 lo)
__device__ __forceinline__ void split_tf32(float x, uint32_t& hi, uint32_t& lo) {
    hi = to_tf32(x);
    lo = to_tf32(x - __uint_as_float(hi));
}

// ---------------------------------------------------------------------------
// Kernel 1: Gram via warp-level tf32 mma.sync (verified R11). 148 x 512.
// ---------------------------------------------------------------------------
__global__ __launch_bounds__(512, 1) void k_stats(const float* __restrict__ X) {
    const int s = blockIdx.x;
    const int g = threadIdx.x >> 5;
    const int lane = threadIdx.x & 31;
    const int row = lane >> 2, q = lane & 3;

    const int units = 21 + (s < 28 ? 1 : 0);
    int p = s * 1344 + (s < 28 ? s : 28) * 64;

    float c[8];
#pragma unroll
    for (int i = 0; i < 8; i++) c[i] = 0.f;
    float slo = 0.f, shi = 0.f;

    const float* gb = X + (size_t)(g * 16 + row) * HWs + 4 * q;

    for (int u = 0; u < units; u++, p += 64) {
        const int n  = p / HWs;
        const int hw = p - n * HWs;
        const float* b0 = gb + (size_t)n * Cc * HWs + hw;
        const float* b1 = b0 + 8 * HWs;

        float4 vlo[4], vhi[4];
#pragma unroll
        for (int i = 0; i < 4; i++) vlo[i] = *(const float4*)(b0 + 16 * i);
#pragma unroll
        for (int i = 0; i < 4; i++) vhi[i] = *(const float4*)(b1 + 16 * i);

#pragma unroll
        for (int i = 0; i < 4; i++) {
            slo += (vlo[i].x + vlo[i].y) + (vlo[i].z + vlo[i].w);
            shi += (vhi[i].x + vhi[i].y) + (vhi[i].z + vhi[i].w);

            uint32_t a0 = to_tf32(vlo[i].x), a1 = to_tf32(vhi[i].x);
            uint32_t a2 = to_tf32(vlo[i].y), a3 = to_tf32(vhi[i].y);
            mma_tf32(c,     a0, a1, a2, a3, a0, a2);
            mma_tf32(c + 4, a0, a1, a2, a3, a1, a3);

            uint32_t e0 = to_tf32(vlo[i].z), e1 = to_tf32(vhi[i].z);
            uint32_t e2 = to_tf32(vlo[i].w), e3 = to_tf32(vhi[i].w);
            mma_tf32(c,     e0, e1, e2, e3, e0, e2);
            mma_tf32(c + 4, e0, e1, e2, e3, e1, e3);
        }
    }

    slo += __shfl_xor_sync(0xffffffffu, slo, 1);
    slo += __shfl_xor_sync(0xffffffffu, slo, 2);
    shi += __shfl_xor_sync(0xffffffffu, shi, 1);
    shi += __shfl_xor_sync(0xffffffffu, shi, 2);
    if (q == 0) {
        g_sum[g][s][row]     = slo;
        g_sum[g][s][row + 8] = shi;
    }

    *(float2*)&g_sig[g][s][row][2 * q]         = make_float2(c[0], c[1]);
    *(float2*)&g_sig[g][s][row + 8][2 * q]     = make_float2(c[2], c[3]);
    *(float2*)&g_sig[g][s][row][8 + 2 * q]     = make_float2(c[4], c[5]);
    *(float2*)&g_sig[g][s][row + 8][8 + 2 * q] = make_float2(c[6], c[7]);
}

// ---------------------------------------------------------------------------
// Kernel 2: partials -> sigma -> Newton-Schulz -> A, beta. 16 x 256.
// ---------------------------------------------------------------------------
__global__ __launch_bounds__(256, 1) void k_wm(const float* __restrict__ wgt,
                                               const float* __restrict__ bia) {
    const int g = blockIdx.x;
    const int t = threadIdx.x;
    const int r = t >> 4, c = t & 15;

    __shared__ float meanS[16];
    __shared__ float sig[16][17], P[16][17], T1[16][17], T2[16][17];

    float sv = 0.f;
    for (int b = 0; b < SLICES; b++) sv += g_sig[g][b][r][c];

    if (t < 16) {
        float a = 0.f;
        for (int b = 0; b < SLICES; b++) a += g_sum[g][b][t];
        meanS[t] = a * (1.0f / Mf);
    }
    __syncthreads();

    sv = sv * (1.0f / Mf) - meanS[r] * meanS[c] + ((r == c) ? EPSf : 0.f);
    sig[r][c] = sv;
    __syncthreads();

    float tr = 0.f;
#pragma unroll
    for (int k = 0; k < 16; k++) tr += sig[k][k];
    __syncthreads();

    sig[r][c] = sv / tr;
    P[r][c] = (r == c) ? 1.f : 0.f;
    __syncthreads();

    for (int it = 0; it < 10; it++) {
        float d1 = 0.f;
#pragma unroll
        for (int k = 0; k < 16; k++) d1 += P[r][k] * P[k][c];
        T1[r][c] = d1;
        __syncthreads();
        float d2 = 0.f;
#pragma unroll
        for (int k = 0; k < 16; k++) d2 += T1[r][k] * P[k][c];
        T2[r][c] = d2;
        __syncthreads();
        float d3 = 0.f;
#pragma unroll
        for (int k = 0; k < 16; k++) d3 += T2[r][k] * sig[k][c];
        P[r][c] = 1.5f * P[r][c] - 0.5f * d3;
        __syncthreads();
    }

    const float wmv = P[r][c] * rsqrtf(tr);
    const float Av  = wgt[g * 16 + r] * wmv;
    g_A[g][r][c] = Av;
    T1[r][c] = Av * meanS[c];
    __syncthreads();
    if (t < 16) {
        float acc = bia[g * 16 + t];
#pragma unroll
        for (int d = 0; d < 16; d++) acc -= T1[t][d];
        g_beta[g][t] = acc;
    }
}

// ---------------------------------------------------------------------------
// Kernel 3: apply via tf32 mma.sync, split precision (Ah*xh + Ah*xl + Al*xh).
// Warp = 16ch x 16pos slab; A fragments in registers (per-group, reloaded on
// column change ~1-2x per warp), x loaded as B fragments (sector-aligned
// LDG.32), beta folded into C init. Contiguous slab ranges per warp.
// ---------------------------------------------------------------------------
__global__ __launch_bounds__(256, 2) void k_apply(const float* __restrict__ X,
                                                  float* __restrict__ Y) {
    const int wid  = (blockIdx.x * 256 + threadIdx.x) >> 5;
    const int lane = threadIdx.x & 31;
    const int row  = lane >> 2, q = lane & 3;

    const int base = wid * BASE_CNT + (wid < 1792 ? wid : 1792);
    const int cnt  = BASE_CNT + (wid < 1792 ? 1 : 0);

    // A fragments (hi/lo) + beta, loaded on column change
    uint32_t ah[8], al[8];
    float br = 0.f, br8 = 0.f;
    int curcol = -1;

    // x buffers: [s-slab 0/1][b-reg 0..3] (b0: d=q, b1: d=q+4, b2: d=q+8, b3: d=q+12)
    float xc[8], xn[8];

    int sl = base;
    {   // initial load
        const int col = sl / SLABS_PER_COL;
        const int pos = (sl - col * SLABS_PER_COL) * 16;
        const float* xb = X + (size_t)col * (16 * HWs) + pos + row;
#pragma unroll
        for (int s = 0; s < 2; s++)
#pragma unroll
            for (int j = 0; j < 4; j++)
                xc[s * 4 + j] = xb[(q + 4 * j) * HWs + 8 * s];
    }

    for (int i = 0; i < cnt; i++) {
        const int col = sl / SLABS_PER_COL;
        const int pos = (sl - col * SLABS_PER_COL) * 16;

        // prefetch next slab's x
        if (i + 1 < cnt) {
            const int nsl  = sl + 1;
            const int ncol = nsl / SLABS_PER_COL;
            const int npos = (nsl - ncol * SLABS_PER_COL) * 16;
            const float* xb = X + (size_t)ncol * (16 * HWs) + npos + row;
#pragma unroll
            for (int s = 0; s < 2; s++)
#pragma unroll
                for (int j = 0; j < 4; j++)
                    xn[s * 4 + j] = xb[(q + 4 * j) * HWs + 8 * s];
        }

        // reload A fragments on column change
        if (col != curcol) {
            curcol = col;
            const int g = col & 15;
            const float* Ag = &g_A[g][0][0];
            // chunk0: k = q, q+4 ; chunk1: k = 8+q, 12+q
            float av[8];
            av[0] = Ag[row * 16 + q];            av[1] = Ag[(row + 8) * 16 + q];
            av[2] = Ag[row * 16 + q + 4];        av[3] = Ag[(row + 8) * 16 + q + 4];
            av[4] = Ag[row * 16 + 8 + q];        av[5] = Ag[(row + 8) * 16 + 8 + q];
            av[6] = Ag[row * 16 + 12 + q];       av[7] = Ag[(row + 8) * 16 + 12 + q];
#pragma unroll
            for (int j = 0; j < 8; j++) split_tf32(av[j], ah[j], al[j]);
            br  = g_beta[g][row];
            br8 = g_beta[g][row + 8];
        }

        // split x
        uint32_t xh[8], xl[8];
#pragma unroll
        for (int j = 0; j < 8; j++) split_tf32(xc[j], xh[j], xl[j]);

        // two n-slabs of 8 positions each
        float c0[4] = {br, br, br8, br8};
        float c1[4] = {br, br, br8, br8};
#pragma unroll
        for (int s = 0; s < 2; s++) {
            float* cc = s ? c1 : c0;
            const int o = 4 * s;
            // chunk0 (d=0..7): b0 = x[d=q], b1 = x[d=q+4]
            mma_tf32(cc, ah[0], ah[1], ah[2], ah[3], xh[o + 0], xh[o + 1]);
            mma_tf32(cc, ah[0], ah[1], ah[2], ah[3], xl[o + 0], xl[o + 1]);
            mma_tf32(cc, al[0], al[1], al[2], al[3], xh[o + 0], xh[o + 1]);
            // chunk1 (d=8..15)
            mma_tf32(cc, ah[4], ah[5], ah[6], ah[7], xh[o + 2], xh[o + 3]);
            mma_tf32(cc, ah[4], ah[5], ah[6], ah[7], xl[o + 2], xl[o + 3]);
            mma_tf32(cc, al[4], al[5], al[6], al[7], xh[o + 2], xh[o + 3]);
        }

        // store: c0/c1 cols = pos + 8s + 2q (+1), rows = row / row+8
        float* yb = Y + (size_t)col * (16 * HWs) + pos;
        *(float2*)(yb + (size_t)row * HWs + 2 * q)            = make_float2(c0[0], c0[1]);
        *(float2*)(yb + (size_t)(row + 8) * HWs + 2 * q)      = make_float2(c0[2], c0[3]);
        *(float2*)(yb + (size_t)row * HWs + 8 + 2 * q)        = make_float2(c1[0], c1[1]);
        *(float2*)(yb + (size_t)(row + 8) * HWs + 8 + 2 * q)  = make_float2(c1[2], c1[3]);

#pragma unroll
        for (int j = 0; j < 8; j++) xc[j] = xn[j];
        sl++;
    }
}

// ---------------------------------------------------------------------------
extern "C" void kernel_launch(void* const* d_in, const int* in_sizes, int n_in,
                              void* d_out, int out_size) {
    const float* X = (const float*)d_in[0];
    const float* W = (const float*)d_in[1];
    const float* B = (const float*)d_in[2];
    float* Y = (float*)d_out;

    k_stats<<<SLICES, 512>>>(X);
    k_wm<<<Gg, 256>>>(W, B);
    k_apply<<<APPLY_BLOCKS, 256>>>(X, Y);
}

// round 13
// speedup vs baseline: 1.0350x; 1.0350x over previous
#include <cuda_runtime.h>
#include <cstdint>

#define Nn   64
#define Cc   256
#define HWs  3136
#define Gg   16
#define Mf   200704.0f
#define EPSf 1e-3f

#define SLICES 148
#define APPLY_BLOCKS 296
#define SLABS_PER_COL 196                // 3136 / 16
#define BASE_CNT 84                      // 84*2368 = 198912; remainder 1792

// Scratch (static device globals — no allocation)
__device__ float g_sig[Gg][SLICES][16][16];
__device__ float g_sum[Gg][SLICES][16];
__device__ float g_A[Gg][16][16];
__device__ float g_beta[Gg][16];

// ---------------- helpers ----------------
__device__ __forceinline__ uint32_t to_tf32(float f) {
    uint32_t u;
    asm("cvt.rna.tf32.f32 %0, %1;" : "=r"(u) : "f"(f));
    return u;
}

__device__ __forceinline__ void mma_tf32(float* c, uint32_t a0, uint32_t a1,
                                         uint32_t a2, uint32_t a3,
                                         uint32_t b0, uint32_t b1) {
    asm("mma.sync.aligned.m16n8k8.row.col.f32.tf32.tf32.f32 "
        "{%0,%1,%2,%3}, {%4,%5,%6,%7}, {%8,%9}, {%0,%1,%2,%3};"
        : "+f"(c[0]), "+f"(c[1]), "+f"(c[2]), "+f"(c[3])
        : "r"(a0), "r"(a1), "r"(a2), "r"(a3), "r"(b0), "r"(b1));
}

__device__ __forceinline__ void split_tf32(float x, uint32_t& hi, uint32_t& lo) {
    hi = to_tf32(x);
    lo = to_tf32(x - __uint_as_float(hi));
}

// ---------------------------------------------------------------------------
// Kernel 1: Gram via warp-level tf32 mma.sync (verified R11). 148 x 512.
// ---------------------------------------------------------------------------
__global__ __launch_bounds__(512, 1) void k_stats(const float* __restrict__ X) {
    const int s = blockIdx.x;
    const int g = threadIdx.x >> 5;
    const int lane = threadIdx.x & 31;
    const int row = lane >> 2, q = lane & 3;

    const int units = 21 + (s < 28 ? 1 : 0);
    int p = s * 1344 + (s < 28 ? s : 28) * 64;

    float c[8];
#pragma unroll
    for (int i = 0; i < 8; i++) c[i] = 0.f;
    float slo = 0.f, shi = 0.f;

    const float* gb = X + (size_t)(g * 16 + row) * HWs + 4 * q;

    for (int u = 0; u < units; u++, p += 64) {
        const int n  = p / HWs;
        const int hw = p - n * HWs;
        const float* b0 = gb + (size_t)n * Cc * HWs + hw;
        const float* b1 = b0 + 8 * HWs;

        float4 vlo[4], vhi[4];
#pragma unroll
        for (int i = 0; i < 4; i++) vlo[i] = *(const float4*)(b0 + 16 * i);
#pragma unroll
        for (int i = 0; i < 4; i++) vhi[i] = *(const float4*)(b1 + 16 * i);

#pragma unroll
        for (int i = 0; i < 4; i++) {
            slo += (vlo[i].x + vlo[i].y) + (vlo[i].z + vlo[i].w);
            shi += (vhi[i].x + vhi[i].y) + (vhi[i].z + vhi[i].w);

            uint32_t a0 = to_tf32(vlo[i].x), a1 = to_tf32(vhi[i].x);
            uint32_t a2 = to_tf32(vlo[i].y), a3 = to_tf32(vhi[i].y);
            mma_tf32(c,     a0, a1, a2, a3, a0, a2);
            mma_tf32(c + 4, a0, a1, a2, a3, a1, a3);

            uint32_t e0 = to_tf32(vlo[i].z), e1 = to_tf32(vhi[i].z);
            uint32_t e2 = to_tf32(vlo[i].w), e3 = to_tf32(vhi[i].w);
            mma_tf32(c,     e0, e1, e2, e3, e0, e2);
            mma_tf32(c + 4, e0, e1, e2, e3, e1, e3);
        }
    }

    slo += __shfl_xor_sync(0xffffffffu, slo, 1);
    slo += __shfl_xor_sync(0xffffffffu, slo, 2);
    shi += __shfl_xor_sync(0xffffffffu, shi, 1);
    shi += __shfl_xor_sync(0xffffffffu, shi, 2);
    if (q == 0) {
        g_sum[g][s][row]     = slo;
        g_sum[g][s][row + 8] = shi;
    }

    *(float2*)&g_sig[g][s][row][2 * q]         = make_float2(c[0], c[1]);
    *(float2*)&g_sig[g][s][row + 8][2 * q]     = make_float2(c[2], c[3]);
    *(float2*)&g_sig[g][s][row][8 + 2 * q]     = make_float2(c[4], c[5]);
    *(float2*)&g_sig[g][s][row + 8][8 + 2 * q] = make_float2(c[6], c[7]);
}

// ---------------------------------------------------------------------------
// Kernel 2: partials -> sigma -> Newton-Schulz -> A, beta. 16 x 256.
// ---------------------------------------------------------------------------
__global__ __launch_bounds__(256, 1) void k_wm(const float* __restrict__ wgt,
                                               const float* __restrict__ bia) {
    const int g = blockIdx.x;
    const int t = threadIdx.x;
    const int r = t >> 4, c = t & 15;

    __shared__ float meanS[16];
    __shared__ float sig[16][17], P[16][17], T1[16][17], T2[16][17];

    float sv = 0.f;
    for (int b = 0; b < SLICES; b++) sv += g_sig[g][b][r][c];

    if (t < 16) {
        float a = 0.f;
        for (int b = 0; b < SLICES; b++) a += g_sum[g][b][t];
        meanS[t] = a * (1.0f / Mf);
    }
    __syncthreads();

    sv = sv * (1.0f / Mf) - meanS[r] * meanS[c] + ((r == c) ? EPSf : 0.f);
    sig[r][c] = sv;
    __syncthreads();

    float tr = 0.f;
#pragma unroll
    for (int k = 0; k < 16; k++) tr += sig[k][k];
    __syncthreads();

    sig[r][c] = sv / tr;
    P[r][c] = (r == c) ? 1.f : 0.f;
    __syncthreads();

    for (int it = 0; it < 10; it++) {
        float d1 = 0.f;
#pragma unroll
        for (int k = 0; k < 16; k++) d1 += P[r][k] * P[k][c];
        T1[r][c] = d1;
        __syncthreads();
        float d2 = 0.f;
#pragma unroll
        for (int k = 0; k < 16; k++) d2 += T1[r][k] * P[k][c];
        T2[r][c] = d2;
        __syncthreads();
        float d3 = 0.f;
#pragma unroll
        for (int k = 0; k < 16; k++) d3 += T2[r][k] * sig[k][c];
        P[r][c] = 1.5f * P[r][c] - 0.5f * d3;
        __syncthreads();
    }

    const float wmv = P[r][c] * rsqrtf(tr);
    const float Av  = wgt[g * 16 + r] * wmv;
    g_A[g][r][c] = Av;
    T1[r][c] = Av * meanS[c];
    __syncthreads();
    if (t < 16) {
        float acc = bia[g * 16 + t];
#pragma unroll
        for (int d = 0; d < 16; d++) acc -= T1[t][d];
        g_beta[g][t] = acc;
    }
}

// ---------------------------------------------------------------------------
// Kernel 3: apply via tf32 mma.sync, split precision. Incremental (col,sin)
// tracking (NO division in the loop), pointer stepping, A-fragment reload
// only at column boundaries, 4 independent 3-deep MMA chains.
// ---------------------------------------------------------------------------
__global__ __launch_bounds__(256, 2) void k_apply(const float* __restrict__ X,
                                                  float* __restrict__ Y) {
    const int wid  = (blockIdx.x * 256 + threadIdx.x) >> 5;
    const int lane = threadIdx.x & 31;
    const int row  = lane >> 2, q = lane & 3;

    const int base = wid * BASE_CNT + (wid < 1792 ? wid : 1792);
    const int cnt  = BASE_CNT + (wid < 1792 ? 1 : 0);

    int col = base / SLABS_PER_COL;                 // one division, warp start
    int sin = base - col * SLABS_PER_COL;

    // per-column state
    uint32_t ah[8], al[8];
    float br, br8;
    const float *xbase;                              // X + col*16*HWs (+ row)
    float *ybase;

#define LOAD_COL(C)                                                            \
    {                                                                          \
        const int _g = (C) & 15;                                               \
        const float* Ag = &g_A[_g][0][0];                                      \
        float av[8];                                                           \
        av[0] = Ag[row * 16 + q];        av[1] = Ag[(row + 8) * 16 + q];       \
        av[2] = Ag[row * 16 + q + 4];    av[3] = Ag[(row + 8) * 16 + q + 4];   \
        av[4] = Ag[row * 16 + 8 + q];    av[5] = Ag[(row + 8) * 16 + 8 + q];   \
        av[6] = Ag[row * 16 + 12 + q];   av[7] = Ag[(row + 8) * 16 + 12 + q];  \
        _Pragma("unroll")                                                      \
        for (int j = 0; j < 8; j++) split_tf32(av[j], ah[j], al[j]);           \
        br  = g_beta[_g][row];                                                 \
        br8 = g_beta[_g][row + 8];                                             \
        xbase = X + (size_t)(C) * (16 * HWs);                                  \
        ybase = Y + (size_t)(C) * (16 * HWs);                                  \
    }

    LOAD_COL(col);

    // x fragment loads for slab at (xb = xbase + pos)
#define LOAD_X(DST, XP)                                                        \
    {                                                                          \
        const float* _p = (XP) + row;                                          \
        _Pragma("unroll")                                                      \
        for (int s = 0; s < 2; s++)                                            \
            _Pragma("unroll")                                                  \
            for (int j = 0; j < 4; j++)                                        \
                (DST)[s * 4 + j] = _p[(q + 4 * j) * HWs + 8 * s];              \
    }

    float xc[8], xn[8];
    LOAD_X(xc, xbase + sin * 16);

    for (int i = 0; i < cnt; i++) {
        const int pos = sin * 16;

        // next slab indices (incremental)
        int nsin = sin + 1, ncol = col;
        if (nsin == SLABS_PER_COL) { nsin = 0; ncol = col + 1; }

        if (i + 1 < cnt) {
            const float* nxb = (ncol == col)
                ? xbase + nsin * 16
                : X + (size_t)ncol * (16 * HWs);     // nsin == 0
            LOAD_X(xn, nxb);
        }

        uint32_t xh[8], xl[8];
#pragma unroll
        for (int j = 0; j < 8; j++) split_tf32(xc[j], xh[j], xl[j]);

        // 4 independent 3-deep chains: (hi, lo) per n-slab
        float cA0[4] = {br, br, br8, br8};
        float cB0[4] = {0.f, 0.f, 0.f, 0.f};
        float cA1[4] = {br, br, br8, br8};
        float cB1[4] = {0.f, 0.f, 0.f, 0.f};

        // n-slab 0 (positions pos..pos+7)
        mma_tf32(cA0, ah[0], ah[1], ah[2], ah[3], xh[0], xh[1]);
        mma_tf32(cB0, ah[0], ah[1], ah[2], ah[3], xl[0], xl[1]);
        mma_tf32(cA0, ah[4], ah[5], ah[6], ah[7], xh[2], xh[3]);
        mma_tf32(cB0, ah[4], ah[5], ah[6], ah[7], xl[2], xl[3]);
        mma_tf32(cA0, al[0], al[1], al[2], al[3], xh[0], xh[1]);
        mma_tf32(cB0, al[4], al[5], al[6], al[7], xh[2], xh[3]);
        // n-slab 1 (positions pos+8..pos+15)
        mma_tf32(cA1, ah[0], ah[1], ah[2], ah[3], xh[4], xh[5]);
        mma_tf32(cB1, ah[0], ah[1], ah[2], ah[3], xl[4], xl[5]);
        mma_tf32(cA1, ah[4], ah[5], ah[6], ah[7], xh[6], xh[7]);
        mma_tf32(cB1, ah[4], ah[5], ah[6], ah[7], xl[6], xl[7]);
        mma_tf32(cA1, al[0], al[1], al[2], al[3], xh[4], xh[5]);
        mma_tf32(cB1, al[4], al[5], al[6], al[7], xh[6], xh[7]);

#pragma unroll
        for (int j = 0; j < 4; j++) { cA0[j] += cB0[j]; cA1[j] += cB1[j]; }

        float* yb = ybase + pos;
        *(float2*)(yb + (size_t)row * HWs + 2 * q)           = make_float2(cA0[0], cA0[1]);
        *(float2*)(yb + (size_t)(row + 8) * HWs + 2 * q)     = make_float2(cA0[2], cA0[3]);
        *(float2*)(yb + (size_t)row * HWs + 8 + 2 * q)       = make_float2(cA1[0], cA1[1]);
        *(float2*)(yb + (size_t)(row + 8) * HWs + 8 + 2 * q) = make_float2(cA1[2], cA1[3]);

#pragma unroll
        for (int j = 0; j < 8; j++) xc[j] = xn[j];
        sin = nsin;
        if (ncol != col) { col = ncol; LOAD_COL(col); }
    }
#undef LOAD_X
#undef LOAD_COL
}

// ---------------------------------------------------------------------------
extern "C" void kernel_launch(void* const* d_in, const int* in_sizes, int n_in,
                              void* d_out, int out_size) {
    const float* X = (const float*)d_in[0];
    const float* W = (const float*)d_in[1];
    const float* B = (const float*)d_in[2];
    float* Y = (float*)d_out;

    k_stats<<<SLICES, 512>>>(X);
    k_wm<<<Gg, 256>>>(W, B);
    k_apply<<<APPLY_BLOCKS, 256>>>(X, Y);
}

// round 14
// speedup vs baseline: 1.0981x; 1.0610x over previous
#include <cuda_runtime.h>
#include <cstdint>

#define Nn   64
#define Cc   256
#define HWs  3136
#define Gg   16
#define Mf   200704.0f
#define EPSf 1e-3f

#define SLICES 148
#define APPLY_BLOCKS 296
#define SLABS_PER_COL 196                // 3136 / 16 (= 98 pairs per column)
#define PAIR_BASE 42                     // pairs per warp; first 896 warps get 43
// total pairs = 100352 = 2368*42 + 896

// Scratch (static device globals — no allocation)
__device__ float g_sig[Gg][SLICES][16][16];
__device__ float g_sum[Gg][SLICES][16];
__device__ float g_A[Gg][16][16];
__device__ float g_beta[Gg][16];

// ---------------- helpers ----------------
__device__ __forceinline__ uint32_t to_tf32(float f) {
    uint32_t u;
    asm("cvt.rna.tf32.f32 %0, %1;" : "=r"(u) : "f"(f));
    return u;
}

__device__ __forceinline__ void mma_tf32(float* c, uint32_t a0, uint32_t a1,
                                         uint32_t a2, uint32_t a3,
                                         uint32_t b0, uint32_t b1) {
    asm("mma.sync.aligned.m16n8k8.row.col.f32.tf32.tf32.f32 "
        "{%0,%1,%2,%3}, {%4,%5,%6,%7}, {%8,%9}, {%0,%1,%2,%3};"
        : "+f"(c[0]), "+f"(c[1]), "+f"(c[2]), "+f"(c[3])
        : "r"(a0), "r"(a1), "r"(a2), "r"(a3), "r"(b0), "r"(b1));
}

__device__ __forceinline__ void split_tf32(float x, uint32_t& hi, uint32_t& lo) {
    hi = to_tf32(x);
    lo = to_tf32(x - __uint_as_float(hi));
}

// ---------------------------------------------------------------------------
// Kernel 1: Gram via warp-level tf32 mma.sync (verified R11). 148 x 512.
// ---------------------------------------------------------------------------
__global__ __launch_bounds__(512, 1) void k_stats(const float* __restrict__ X) {
    const int s = blockIdx.x;
    const int g = threadIdx.x >> 5;
    const int lane = threadIdx.x & 31;
    const int row = lane >> 2, q = lane & 3;

    const int units = 21 + (s < 28 ? 1 : 0);
    int p = s * 1344 + (s < 28 ? s : 28) * 64;

    float c[8];
#pragma unroll
    for (int i = 0; i < 8; i++) c[i] = 0.f;
    float slo = 0.f, shi = 0.f;

    const float* gb = X + (size_t)(g * 16 + row) * HWs + 4 * q;

    for (int u = 0; u < units; u++, p += 64) {
        const int n  = p / HWs;
        const int hw = p - n * HWs;
        const float* b0 = gb + (size_t)n * Cc * HWs + hw;
        const float* b1 = b0 + 8 * HWs;

        float4 vlo[4], vhi[4];
#pragma unroll
        for (int i = 0; i < 4; i++) vlo[i] = *(const float4*)(b0 + 16 * i);
#pragma unroll
        for (int i = 0; i < 4; i++) vhi[i] = *(const float4*)(b1 + 16 * i);

#pragma unroll
        for (int i = 0; i < 4; i++) {
            slo += (vlo[i].x + vlo[i].y) + (vlo[i].z + vlo[i].w);
            shi += (vhi[i].x + vhi[i].y) + (vhi[i].z + vhi[i].w);

            uint32_t a0 = to_tf32(vlo[i].x), a1 = to_tf32(vhi[i].x);
            uint32_t a2 = to_tf32(vlo[i].y), a3 = to_tf32(vhi[i].y);
            mma_tf32(c,     a0, a1, a2, a3, a0, a2);
            mma_tf32(c + 4, a0, a1, a2, a3, a1, a3);

            uint32_t e0 = to_tf32(vlo[i].z), e1 = to_tf32(vhi[i].z);
            uint32_t e2 = to_tf32(vlo[i].w), e3 = to_tf32(vhi[i].w);
            mma_tf32(c,     e0, e1, e2, e3, e0, e2);
            mma_tf32(c + 4, e0, e1, e2, e3, e1, e3);
        }
    }

    slo += __shfl_xor_sync(0xffffffffu, slo, 1);
    slo += __shfl_xor_sync(0xffffffffu, slo, 2);
    shi += __shfl_xor_sync(0xffffffffu, shi, 1);
    shi += __shfl_xor_sync(0xffffffffu, shi, 2);
    if (q == 0) {
        g_sum[g][s][row]     = slo;
        g_sum[g][s][row + 8] = shi;
    }

    *(float2*)&g_sig[g][s][row][2 * q]         = make_float2(c[0], c[1]);
    *(float2*)&g_sig[g][s][row + 8][2 * q]     = make_float2(c[2], c[3]);
    *(float2*)&g_sig[g][s][row][8 + 2 * q]     = make_float2(c[4], c[5]);
    *(float2*)&g_sig[g][s][row + 8][8 + 2 * q] = make_float2(c[6], c[7]);
}

// ---------------------------------------------------------------------------
// Kernel 2: partials -> sigma -> Newton-Schulz -> A, beta. 16 x 256.
// ---------------------------------------------------------------------------
__global__ __launch_bounds__(256, 1) void k_wm(const float* __restrict__ wgt,
                                               const float* __restrict__ bia) {
    const int g = blockIdx.x;
    const int t = threadIdx.x;
    const int r = t >> 4, c = t & 15;

    __shared__ float meanS[16];
    __shared__ float sig[16][17], P[16][17], T1[16][17], T2[16][17];

    float sv = 0.f;
    for (int b = 0; b < SLICES; b++) sv += g_sig[g][b][r][c];

    if (t < 16) {
        float a = 0.f;
        for (int b = 0; b < SLICES; b++) a += g_sum[g][b][t];
        meanS[t] = a * (1.0f / Mf);
    }
    __syncthreads();

    sv = sv * (1.0f / Mf) - meanS[r] * meanS[c] + ((r == c) ? EPSf : 0.f);
    sig[r][c] = sv;
    __syncthreads();

    float tr = 0.f;
#pragma unroll
    for (int k = 0; k < 16; k++) tr += sig[k][k];
    __syncthreads();

    sig[r][c] = sv / tr;
    P[r][c] = (r == c) ? 1.f : 0.f;
    __syncthreads();

    for (int it = 0; it < 10; it++) {
        float d1 = 0.f;
#pragma unroll
        for (int k = 0; k < 16; k++) d1 += P[r][k] * P[k][c];
        T1[r][c] = d1;
        __syncthreads();
        float d2 = 0.f;
#pragma unroll
        for (int k = 0; k < 16; k++) d2 += T1[r][k] * P[k][c];
        T2[r][c] = d2;
        __syncthreads();
        float d3 = 0.f;
#pragma unroll
        for (int k = 0; k < 16; k++) d3 += T2[r][k] * sig[k][c];
        P[r][c] = 1.5f * P[r][c] - 0.5f * d3;
        __syncthreads();
    }

    const float wmv = P[r][c] * rsqrtf(tr);
    const float Av  = wgt[g * 16 + r] * wmv;
    g_A[g][r][c] = Av;
    T1[r][c] = Av * meanS[c];
    __syncthreads();
    if (t < 16) {
        float acc = bia[g * 16 + t];
#pragma unroll
        for (int d = 0; d < 16; d++) acc -= T1[t][d];
        g_beta[g][t] = acc;
    }
}

// ---------------------------------------------------------------------------
// Kernel 3: apply via tf32 mma.sync, split precision, SLAB-PAIR iteration:
// 16 LDG.32 prefetched per pair (2 KB/warp in flight -> 32 KB/SM) to cover
// DRAM latency. Pairs never straddle a column (196 slabs/col is even and
// warp base slab is even), so A fragments are pair-invariant.
// ---------------------------------------------------------------------------
__global__ __launch_bounds__(256, 2) void k_apply(const float* __restrict__ X,
                                                  float* __restrict__ Y) {
    const int wid  = (blockIdx.x * 256 + threadIdx.x) >> 5;
    const int lane = threadIdx.x & 31;
    const int row  = lane >> 2, q = lane & 3;

    const int pbase = wid * PAIR_BASE + (wid < 896 ? wid : 896);
    const int pcnt  = PAIR_BASE + (wid < 896 ? 1 : 0);

    const int base = 2 * pbase;                      // even slab index
    int col = base / SLABS_PER_COL;                  // one division, warp start
    int sin = base - col * SLABS_PER_COL;            // even

    uint32_t ah[8], al[8];
    float br, br8;
    const float* xbase;
    float* ybase;

#define LOAD_COL(C)                                                            \
    {                                                                          \
        const int _g = (C) & 15;                                               \
        const float* Ag = &g_A[_g][0][0];                                      \
        float av[8];                                                           \
        av[0] = Ag[row * 16 + q];        av[1] = Ag[(row + 8) * 16 + q];       \
        av[2] = Ag[row * 16 + q + 4];    av[3] = Ag[(row + 8) * 16 + q + 4];   \
        av[4] = Ag[row * 16 + 8 + q];    av[5] = Ag[(row + 8) * 16 + 8 + q];   \
        av[6] = Ag[row * 16 + 12 + q];   av[7] = Ag[(row + 8) * 16 + 12 + q];  \
        _Pragma("unroll")                                                      \
        for (int j = 0; j < 8; j++) split_tf32(av[j], ah[j], al[j]);           \
        br  = g_beta[_g][row];                                                 \
        br8 = g_beta[_g][row + 8];                                             \
        xbase = X + (size_t)(C) * (16 * HWs);                                  \
        ybase = Y + (size_t)(C) * (16 * HWs);                                  \
    }

    // load x fragments for the PAIR starting at position XP (16 floats)
#define LOAD_PAIR(DST, XP)                                                     \
    {                                                                          \
        const float* _p = (XP) + row;                                          \
        _Pragma("unroll")                                                      \
        for (int s = 0; s < 4; s++)                                            \
            _Pragma("unroll")                                                  \
            for (int j = 0; j < 4; j++)                                        \
                (DST)[s * 4 + j] = _p[(q + 4 * j) * HWs + 8 * s];              \
    }

    // compute + store one slab (8 x values xs[8], output at yb)
#define DO_SLAB(XS, YB)                                                        \
    {                                                                          \
        uint32_t xh[8], xl[8];                                                 \
        _Pragma("unroll")                                                      \
        for (int j = 0; j < 8; j++) split_tf32((XS)[j], xh[j], xl[j]);         \
        float cA0[4] = {br, br, br8, br8};                                     \
        float cB0[4] = {0.f, 0.f, 0.f, 0.f};                                   \
        float cA1[4] = {br, br, br8, br8};                                     \
        float cB1[4] = {0.f, 0.f, 0.f, 0.f};                                   \
        mma_tf32(cA0, ah[0], ah[1], ah[2], ah[3], xh[0], xh[1]);               \
        mma_tf32(cB0, ah[0], ah[1], ah[2], ah[3], xl[0], xl[1]);               \
        mma_tf32(cA0, ah[4], ah[5], ah[6], ah[7], xh[2], xh[3]);               \
        mma_tf32(cB0, ah[4], ah[5], ah[6], ah[7], xl[2], xl[3]);               \
        mma_tf32(cA0, al[0], al[1], al[2], al[3], xh[0], xh[1]);               \
        mma_tf32(cB0, al[4], al[5], al[6], al[7], xh[2], xh[3]);               \
        mma_tf32(cA1, ah[0], ah[1], ah[2], ah[3], xh[4], xh[5]);               \
        mma_tf32(cB1, ah[0], ah[1], ah[2], ah[3], xl[4], xl[5]);               \
        mma_tf32(cA1, ah[4], ah[5], ah[6], ah[7], xh[6], xh[7]);               \
        mma_tf32(cB1, ah[4], ah[5], ah[6], ah[7], xl[6], xl[7]);               \
        mma_tf32(cA1, al[0], al[1], al[2], al[3], xh[4], xh[5]);               \
        mma_tf32(cB1, al[4], al[5], al[6], al[7], xh[6], xh[7]);               \
        _Pragma("unroll")                                                      \
        for (int j = 0; j < 4; j++) { cA0[j] += cB0[j]; cA1[j] += cB1[j]; }    \
        float* _y = (YB);                                                      \
        *(float2*)(_y + (size_t)row * HWs + 2 * q)           = make_float2(cA0[0], cA0[1]); \
        *(float2*)(_y + (size_t)(row + 8) * HWs + 2 * q)     = make_float2(cA0[2], cA0[3]); \
        *(float2*)(_y + (size_t)row * HWs + 8 + 2 * q)       = make_float2(cA1[0], cA1[1]); \
        *(float2*)(_y + (size_t)(row + 8) * HWs + 8 + 2 * q) = make_float2(cA1[2], cA1[3]); \
    }

    LOAD_COL(col);

    float xc[16], xn[16];
    LOAD_PAIR(xc, xbase + sin * 16);

    for (int i = 0; i < pcnt; i++) {
        const int pos = sin * 16;

        // next pair indices (incremental; pairs never straddle columns)
        int nsin = sin + 2, ncol = col;
        if (nsin == SLABS_PER_COL) { nsin = 0; ncol = col + 1; }

        if (i + 1 < pcnt) {
            const float* nxb = (ncol == col)
                ? xbase + nsin * 16
                : X + (size_t)ncol * (16 * HWs);
            LOAD_PAIR(xn, nxb);
        }

        DO_SLAB(xc,     ybase + pos);
        DO_SLAB(xc + 8, ybase + pos + 16);

#pragma unroll
        for (int j = 0; j < 16; j++) xc[j] = xn[j];
        sin = nsin;
        if (ncol != col) { col = ncol; LOAD_COL(col); }
    }
#undef DO_SLAB
#undef LOAD_PAIR
#undef LOAD_COL
}

// ---------------------------------------------------------------------------
extern "C" void kernel_launch(void* const* d_in, const int* in_sizes, int n_in,
                              void* d_out, int out_size) {
    const float* X = (const float*)d_in[0];
    const float* W = (const float*)d_in[1];
    const float* B = (const float*)d_in[2];
    float* Y = (float*)d_out;

    k_stats<<<SLICES, 512>>>(X);
    k_wm<<<Gg, 256>>>(W, B);
    k_apply<<<APPLY_BLOCKS, 256>>>(X, Y);
}

// round 15
// speedup vs baseline: 1.2186x; 1.1097x over previous
#include <cuda_runtime.h>
#include <cstdint>

#define Nn   64
#define Cc   256
#define HWs  3136
#define Gg   16
#define Mf   200704.0f
#define EPSf 1e-3f

#define SLICES 148
#define HW4       784
#define TOT_TASKS (Nn * Gg * HW4)
#define APPLY_BLOCKS 296

// Scratch (static device globals — no allocation)
__device__ float g_sig[Gg][SLICES][16][16];
__device__ float g_sum[Gg][SLICES][16];
__device__ float g_A[Gg][16][16];
__device__ float g_beta[Gg][16];

// ---------------- helpers ----------------
__device__ __forceinline__ uint32_t to_tf32(float f) {
    uint32_t u;
    asm("cvt.rna.tf32.f32 %0, %1;" : "=r"(u) : "f"(f));
    return u;
}

__device__ __forceinline__ void mma_tf32(float* c, uint32_t a0, uint32_t a1,
                                         uint32_t a2, uint32_t a3,
                                         uint32_t b0, uint32_t b1) {
    asm("mma.sync.aligned.m16n8k8.row.col.f32.tf32.tf32.f32 "
        "{%0,%1,%2,%3}, {%4,%5,%6,%7}, {%8,%9}, {%0,%1,%2,%3};"
        : "+f"(c[0]), "+f"(c[1]), "+f"(c[2]), "+f"(c[3])
        : "r"(a0), "r"(a1), "r"(a2), "r"(a3), "r"(b0), "r"(b1));
}

// ---------------------------------------------------------------------------
// Kernel 1: Gram via warp-level tf32 mma.sync (verified R11). 148 x 512.
// ---------------------------------------------------------------------------
__global__ __launch_bounds__(512, 1) void k_stats(const float* __restrict__ X) {
    const int s = blockIdx.x;
    const int g = threadIdx.x >> 5;
    const int lane = threadIdx.x & 31;
    const int row = lane >> 2, q = lane & 3;

    const int units = 21 + (s < 28 ? 1 : 0);
    int p = s * 1344 + (s < 28 ? s : 28) * 64;

    float c[8];
#pragma unroll
    for (int i = 0; i < 8; i++) c[i] = 0.f;
    float slo = 0.f, shi = 0.f;

    const float* gb = X + (size_t)(g * 16 + row) * HWs + 4 * q;

    for (int u = 0; u < units; u++, p += 64) {
        const int n  = p / HWs;
        const int hw = p - n * HWs;
        const float* b0 = gb + (size_t)n * Cc * HWs + hw;
        const float* b1 = b0 + 8 * HWs;

        float4 vlo[4], vhi[4];
#pragma unroll
        for (int i = 0; i < 4; i++) vlo[i] = *(const float4*)(b0 + 16 * i);
#pragma unroll
        for (int i = 0; i < 4; i++) vhi[i] = *(const float4*)(b1 + 16 * i);

#pragma unroll
        for (int i = 0; i < 4; i++) {
            slo += (vlo[i].x + vlo[i].y) + (vlo[i].z + vlo[i].w);
            shi += (vhi[i].x + vhi[i].y) + (vhi[i].z + vhi[i].w);

            uint32_t a0 = to_tf32(vlo[i].x), a1 = to_tf32(vhi[i].x);
            uint32_t a2 = to_tf32(vlo[i].y), a3 = to_tf32(vhi[i].y);
            mma_tf32(c,     a0, a1, a2, a3, a0, a2);
            mma_tf32(c + 4, a0, a1, a2, a3, a1, a3);

            uint32_t e0 = to_tf32(vlo[i].z), e1 = to_tf32(vhi[i].z);
            uint32_t e2 = to_tf32(vlo[i].w), e3 = to_tf32(vhi[i].w);
            mma_tf32(c,     e0, e1, e2, e3, e0, e2);
            mma_tf32(c + 4, e0, e1, e2, e3, e1, e3);
        }
    }

    slo += __shfl_xor_sync(0xffffffffu, slo, 1);
    slo += __shfl_xor_sync(0xffffffffu, slo, 2);
    shi += __shfl_xor_sync(0xffffffffu, shi, 1);
    shi += __shfl_xor_sync(0xffffffffu, shi, 2);
    if (q == 0) {
        g_sum[g][s][row]     = slo;
        g_sum[g][s][row + 8] = shi;
    }

    *(float2*)&g_sig[g][s][row][2 * q]         = make_float2(c[0], c[1]);
    *(float2*)&g_sig[g][s][row + 8][2 * q]     = make_float2(c[2], c[3]);
    *(float2*)&g_sig[g][s][row][8 + 2 * q]     = make_float2(c[4], c[5]);
    *(float2*)&g_sig[g][s][row + 8][8 + 2 * q] = make_float2(c[6], c[7]);
}

// ---------------------------------------------------------------------------
// Kernel 2: partials -> sigma -> Newton-Schulz -> A, beta. 16 x 256.
// ---------------------------------------------------------------------------
__global__ __launch_bounds__(256, 1) void k_wm(const float* __restrict__ wgt,
                                               const float* __restrict__ bia) {
    const int g = blockIdx.x;
    const int t = threadIdx.x;
    const int r = t >> 4, c = t & 15;

    __shared__ float meanS[16];
    __shared__ float sig[16][17], P[16][17], T1[16][17], T2[16][17];

    float sv = 0.f;
    for (int b = 0; b < SLICES; b++) sv += g_sig[g][b][r][c];

    if (t < 16) {
        float a = 0.f;
        for (int b = 0; b < SLICES; b++) a += g_sum[g][b][t];
        meanS[t] = a * (1.0f / Mf);
    }
    __syncthreads();

    sv = sv * (1.0f / Mf) - meanS[r] * meanS[c] + ((r == c) ? EPSf : 0.f);
    sig[r][c] = sv;
    __syncthreads();

    float tr = 0.f;
#pragma unroll
    for (int k = 0; k < 16; k++) tr += sig[k][k];
    __syncthreads();

    sig[r][c] = sv / tr;
    P[r][c] = (r == c) ? 1.f : 0.f;
    __syncthreads();

    for (int it = 0; it < 10; it++) {
        float d1 = 0.f;
#pragma unroll
        for (int k = 0; k < 16; k++) d1 += P[r][k] * P[k][c];
        T1[r][c] = d1;
        __syncthreads();
        float d2 = 0.f;
#pragma unroll
        for (int k = 0; k < 16; k++) d2 += T1[r][k] * P[k][c];
        T2[r][c] = d2;
        __syncthreads();
        float d3 = 0.f;
#pragma unroll
        for (int k = 0; k < 16; k++) d3 += T2[r][k] * sig[k][c];
        P[r][c] = 1.5f * P[r][c] - 0.5f * d3;
        __syncthreads();
    }

    const float wmv = P[r][c] * rsqrtf(tr);
    const float Av  = wgt[g * 16 + r] * wmv;
    g_A[g][r][c] = Av;
    T1[r][c] = Av * meanS[c];
    __syncthreads();
    if (t < 16) {
        float acc = bia[g * 16 + t];
#pragma unroll
        for (int d = 0; d < 16; d++) acc -= T1[t][d];
        g_beta[g][t] = acc;
    }
}

// ---------------------------------------------------------------------------
// Kernel 3: apply out = A*v + beta. Scalar fp32 (verified-best structure),
// with A consumed as LDS.128 uniform-broadcast quads: per d-quad load 4 x
// float4s, then per channel one float4 A-row-quad + 16 FFMA. LDS count per
// task drops 272 -> 80 (~14% fewer issue slots). 296 blocks x 256, occ 2.
// ---------------------------------------------------------------------------
__global__ __launch_bounds__(256, 2) void k_apply(const float* __restrict__ X,
                                                  float* __restrict__ Y) {
    __shared__ float As[Gg * 256];   // As[g*256 + c*16 + d]
    __shared__ float Bs[Gg * 16];

    for (int i = threadIdx.x; i < Gg * 256; i += 256)
        As[i] = ((const float*)g_A)[i];
    Bs[threadIdx.x] = ((const float*)g_beta)[threadIdx.x];
    __syncthreads();

    const int stride = APPLY_BLOCKS * 256;
    for (int t = blockIdx.x * 256 + threadIdx.x; t < TOT_TASKS; t += stride) {
        const int col = t / HW4;
        const int q   = t - col * HW4;
        const int g   = col & 15;
        const int n   = col >> 4;

        const size_t off = ((size_t)n * Cc + (size_t)g * 16) * HWs;
        const float4* xb = (const float4*)(X + off) + q;
        float4*       yb = (float4*)(Y + off) + q;
        const float*  Ag = As + g * 256;
        const float*  Bg = Bs + g * 16;

        float4 acc[16];
#pragma unroll
        for (int c = 0; c < 16; c++) {
            const float b = Bg[c];
            acc[c].x = b; acc[c].y = b; acc[c].z = b; acc[c].w = b;
        }

#pragma unroll
        for (int dq = 0; dq < 4; dq++) {
            const float4 xv0 = xb[(4 * dq + 0) * HW4];
            const float4 xv1 = xb[(4 * dq + 1) * HW4];
            const float4 xv2 = xb[(4 * dq + 2) * HW4];
            const float4 xv3 = xb[(4 * dq + 3) * HW4];
#pragma unroll
            for (int c = 0; c < 16; c++) {
                const float4 a4 = *(const float4*)(Ag + c * 16 + 4 * dq);
                acc[c].x = fmaf(a4.x, xv0.x, acc[c].x);
                acc[c].y = fmaf(a4.x, xv0.y, acc[c].y);
                acc[c].z = fmaf(a4.x, xv0.z, acc[c].z);
                acc[c].w = fmaf(a4.x, xv0.w, acc[c].w);
                acc[c].x = fmaf(a4.y, xv1.x, acc[c].x);
                acc[c].y = fmaf(a4.y, xv1.y, acc[c].y);
                acc[c].z = fmaf(a4.y, xv1.z, acc[c].z);
                acc[c].w = fmaf(a4.y, xv1.w, acc[c].w);
                acc[c].x = fmaf(a4.z, xv2.x, acc[c].x);
                acc[c].y = fmaf(a4.z, xv2.y, acc[c].y);
                acc[c].z = fmaf(a4.z, xv2.z, acc[c].z);
                acc[c].w = fmaf(a4.z, xv2.w, acc[c].w);
                acc[c].x = fmaf(a4.w, xv3.x, acc[c].x);
                acc[c].y = fmaf(a4.w, xv3.y, acc[c].y);
                acc[c].z = fmaf(a4.w, xv3.z, acc[c].z);
                acc[c].w = fmaf(a4.w, xv3.w, acc[c].w);
            }
        }
#pragma unroll
        for (int c = 0; c < 16; c++)
            yb[c * HW4] = acc[c];
    }
}

// ---------------------------------------------------------------------------
extern "C" void kernel_launch(void* const* d_in, const int* in_sizes, int n_in,
                              void* d_out, int out_size) {
    const float* X = (const float*)d_in[0];
    const float* W = (const float*)d_in[1];
    const float* B = (const float*)d_in[2];
    float* Y = (float*)d_out;

    k_stats<<<SLICES, 512>>>(X);
    k_wm<<<Gg, 256>>>(W, B);
    k_apply<<<APPLY_BLOCKS, 256>>>(X, Y);
}

// round 16
// speedup vs baseline: 1.2312x; 1.0103x over previous
#include <cuda_runtime.h>
#include <cstdint>

#define Nn   64
#define Cc   256
#define HWs  3136
#define Gg   16
#define Mf   200704.0f
#define EPSf 1e-3f

#define SLICES 148
#define HW4       784
#define TOT_TASKS (Nn * Gg * HW4)
#define APPLY_BLOCKS 296

// Scratch (static device globals — no allocation)
__device__ float g_sig[Gg][SLICES][16][16];
__device__ float g_sum[Gg][SLICES][16];
__device__ float g_A[Gg][16][16];
__device__ float g_beta[Gg][16];

// ---------------- helpers ----------------
__device__ __forceinline__ uint32_t to_tf32(float f) {
    uint32_t u;
    asm("cvt.rna.tf32.f32 %0, %1;" : "=r"(u) : "f"(f));
    return u;
}

__device__ __forceinline__ void mma_tf32(float* c, uint32_t a0, uint32_t a1,
                                         uint32_t a2, uint32_t a3,
                                         uint32_t b0, uint32_t b1) {
    asm("mma.sync.aligned.m16n8k8.row.col.f32.tf32.tf32.f32 "
        "{%0,%1,%2,%3}, {%4,%5,%6,%7}, {%8,%9}, {%0,%1,%2,%3};"
        : "+f"(c[0]), "+f"(c[1]), "+f"(c[2]), "+f"(c[3])
        : "r"(a0), "r"(a1), "r"(a2), "r"(a3), "r"(b0), "r"(b1));
}

// ---------------------------------------------------------------------------
// Kernel 1: Gram via warp-level tf32 mma.sync (verified R11). 148 x 512.
// Streaming loads (.cs) + incremental position tracking (no division).
// ---------------------------------------------------------------------------
__global__ __launch_bounds__(512, 1) void k_stats(const float* __restrict__ X) {
    const int s = blockIdx.x;
    const int g = threadIdx.x >> 5;
    const int lane = threadIdx.x & 31;
    const int row = lane >> 2, q = lane & 3;

    const int units = 21 + (s < 28 ? 1 : 0);
    const int p0 = s * 1344 + (s < 28 ? s : 28) * 64;

    float c[8];
#pragma unroll
    for (int i = 0; i < 8; i++) c[i] = 0.f;
    float slo = 0.f, shi = 0.f;

    // initial (n, hw) from p0 — one division per warp
    int n  = p0 / HWs;
    int hw = p0 - n * HWs;                  // multiple of 64
    const float* b0 = X + (size_t)n * Cc * HWs
                        + (size_t)(g * 16 + row) * HWs + hw + 4 * q;

    for (int u = 0; u < units; u++) {
        const float* b1 = b0 + 8 * HWs;

        float4 vlo[4], vhi[4];
#pragma unroll
        for (int i = 0; i < 4; i++) vlo[i] = __ldcs((const float4*)(b0 + 16 * i));
#pragma unroll
        for (int i = 0; i < 4; i++) vhi[i] = __ldcs((const float4*)(b1 + 16 * i));

#pragma unroll
        for (int i = 0; i < 4; i++) {
            slo += (vlo[i].x + vlo[i].y) + (vlo[i].z + vlo[i].w);
            shi += (vhi[i].x + vhi[i].y) + (vhi[i].z + vhi[i].w);

            uint32_t a0 = to_tf32(vlo[i].x), a1 = to_tf32(vhi[i].x);
            uint32_t a2 = to_tf32(vlo[i].y), a3 = to_tf32(vhi[i].y);
            mma_tf32(c,     a0, a1, a2, a3, a0, a2);
            mma_tf32(c + 4, a0, a1, a2, a3, a1, a3);

            uint32_t e0 = to_tf32(vlo[i].z), e1 = to_tf32(vhi[i].z);
            uint32_t e2 = to_tf32(vlo[i].w), e3 = to_tf32(vhi[i].w);
            mma_tf32(c,     e0, e1, e2, e3, e0, e2);
            mma_tf32(c + 4, e0, e1, e2, e3, e1, e3);
        }

        // incremental advance (3136 % 64 == 0, wraps are exact)
        hw += 64;
        if (hw == HWs) {
            hw = 0;
            b0 += 64 + (size_t)(Cc - 1) * HWs;
        } else {
            b0 += 64;
        }
    }

    slo += __shfl_xor_sync(0xffffffffu, slo, 1);
    slo += __shfl_xor_sync(0xffffffffu, slo, 2);
    shi += __shfl_xor_sync(0xffffffffu, shi, 1);
    shi += __shfl_xor_sync(0xffffffffu, shi, 2);
    if (q == 0) {
        g_sum[g][s][row]     = slo;
        g_sum[g][s][row + 8] = shi;
    }

    *(float2*)&g_sig[g][s][row][2 * q]         = make_float2(c[0], c[1]);
    *(float2*)&g_sig[g][s][row + 8][2 * q]     = make_float2(c[2], c[3]);
    *(float2*)&g_sig[g][s][row][8 + 2 * q]     = make_float2(c[4], c[5]);
    *(float2*)&g_sig[g][s][row + 8][8 + 2 * q] = make_float2(c[6], c[7]);
}

// ---------------------------------------------------------------------------
// Kernel 2: partials -> sigma -> Newton-Schulz -> A, beta. 16 x 256.
// ---------------------------------------------------------------------------
__global__ __launch_bounds__(256, 1) void k_wm(const float* __restrict__ wgt,
                                               const float* __restrict__ bia) {
    const int g = blockIdx.x;
    const int t = threadIdx.x;
    const int r = t >> 4, c = t & 15;

    __shared__ float meanS[16];
    __shared__ float sig[16][17], P[16][17], T1[16][17], T2[16][17];

    float sv = 0.f;
    for (int b = 0; b < SLICES; b++) sv += g_sig[g][b][r][c];

    if (t < 16) {
        float a = 0.f;
        for (int b = 0; b < SLICES; b++) a += g_sum[g][b][t];
        meanS[t] = a * (1.0f / Mf);
    }
    __syncthreads();

    sv = sv * (1.0f / Mf) - meanS[r] * meanS[c] + ((r == c) ? EPSf : 0.f);
    sig[r][c] = sv;
    __syncthreads();

    float tr = 0.f;
#pragma unroll
    for (int k = 0; k < 16; k++) tr += sig[k][k];
    __syncthreads();

    sig[r][c] = sv / tr;
    P[r][c] = (r == c) ? 1.f : 0.f;
    __syncthreads();

    for (int it = 0; it < 10; it++) {
        float d1 = 0.f;
#pragma unroll
        for (int k = 0; k < 16; k++) d1 += P[r][k] * P[k][c];
        T1[r][c] = d1;
        __syncthreads();
        float d2 = 0.f;
#pragma unroll
        for (int k = 0; k < 16; k++) d2 += T1[r][k] * P[k][c];
        T2[r][c] = d2;
        __syncthreads();
        float d3 = 0.f;
#pragma unroll
        for (int k = 0; k < 16; k++) d3 += T2[r][k] * sig[k][c];
        P[r][c] = 1.5f * P[r][c] - 0.5f * d3;
        __syncthreads();
    }

    const float wmv = P[r][c] * rsqrtf(tr);
    const float Av  = wgt[g * 16 + r] * wmv;
    g_A[g][r][c] = Av;
    T1[r][c] = Av * meanS[c];
    __syncthreads();
    if (t < 16) {
        float acc = bia[g * 16 + t];
#pragma unroll
        for (int d = 0; d < 16; d++) acc -= T1[t][d];
        g_beta[g][t] = acc;
    }
}

// ---------------------------------------------------------------------------
// Kernel 3: apply out = A*v + beta. Scalar fp32, LDS.128 A-quads, streaming
// loads/stores (.cs — X and Y touched exactly once). 296 x 256, occ 2.
// ---------------------------------------------------------------------------
__global__ __launch_bounds__(256, 2) void k_apply(const float* __restrict__ X,
                                                  float* __restrict__ Y) {
    __shared__ float As[Gg * 256];   // As[g*256 + c*16 + d]
    __shared__ float Bs[Gg * 16];

    for (int i = threadIdx.x; i < Gg * 256; i += 256)
        As[i] = ((const float*)g_A)[i];
    Bs[threadIdx.x] = ((const float*)g_beta)[threadIdx.x];
    __syncthreads();

    const int stride = APPLY_BLOCKS * 256;
    for (int t = blockIdx.x * 256 + threadIdx.x; t < TOT_TASKS; t += stride) {
        const int col = t / HW4;
        const int q   = t - col * HW4;
        const int g   = col & 15;
        const int n   = col >> 4;

        const size_t off = ((size_t)n * Cc + (size_t)g * 16) * HWs;
        const float4* xb = (const float4*)(X + off) + q;
        float4*       yb = (float4*)(Y + off) + q;
        const float*  Ag = As + g * 256;
        const float*  Bg = Bs + g * 16;

        float4 acc[16];
#pragma unroll
        for (int c = 0; c < 16; c++) {
            const float b = Bg[c];
            acc[c].x = b; acc[c].y = b; acc[c].z = b; acc[c].w = b;
        }

#pragma unroll
        for (int dq = 0; dq < 4; dq++) {
            const float4 xv0 = __ldcs(xb + (4 * dq + 0) * HW4);
            const float4 xv1 = __ldcs(xb + (4 * dq + 1) * HW4);
            const float4 xv2 = __ldcs(xb + (4 * dq + 2) * HW4);
            const float4 xv3 = __ldcs(xb + (4 * dq + 3) * HW4);
#pragma unroll
            for (int c = 0; c < 16; c++) {
                const float4 a4 = *(const float4*)(Ag + c * 16 + 4 * dq);
                acc[c].x = fmaf(a4.x, xv0.x, acc[c].x);
                acc[c].y = fmaf(a4.x, xv0.y, acc[c].y);
                acc[c].z = fmaf(a4.x, xv0.z, acc[c].z);
                acc[c].w = fmaf(a4.x, xv0.w, acc[c].w);
                acc[c].x = fmaf(a4.y, xv1.x, acc[c].x);
                acc[c].y = fmaf(a4.y, xv1.y, acc[c].y);
                acc[c].z = fmaf(a4.y, xv1.z, acc[c].z);
                acc[c].w = fmaf(a4.y, xv1.w, acc[c].w);
                acc[c].x = fmaf(a4.z, xv2.x, acc[c].x);
                acc[c].y = fmaf(a4.z, xv2.y, acc[c].y);
                acc[c].z = fmaf(a4.z, xv2.z, acc[c].z);
                acc[c].w = fmaf(a4.z, xv2.w, acc[c].w);
                acc[c].x = fmaf(a4.w, xv3.x, acc[c].x);
                acc[c].y = fmaf(a4.w, xv3.y, acc[c].y);
                acc[c].z = fmaf(a4.w, xv3.z, acc[c].z);
                acc[c].w = fmaf(a4.w, xv3.w, acc[c].w);
            }
        }
#pragma unroll
        for (int c = 0; c < 16; c++)
            __stcs(yb + c * HW4, acc[c]);
    }
}

// ---------------------------------------------------------------------------
extern "C" void kernel_launch(void* const* d_in, const int* in_sizes, int n_in,
                              void* d_out, int out_size) {
    const float* X = (const float*)d_in[0];
    const float* W = (const float*)d_in[1];
    const float* B = (const float*)d_in[2];
    float* Y = (float*)d_out;

    k_stats<<<SLICES, 512>>>(X);
    k_wm<<<Gg, 256>>>(W, B);
    k_apply<<<APPLY_BLOCKS, 256>>>(X, Y);
}